// round 6
// baseline (speedup 1.0000x reference)
#include <cuda_runtime.h>
#include <cuda_bf16.h>
#include <cstdint>

// ---------------- problem constants ----------------
#define B_   8
#define Q_   512
#define C_   2048
#define H_   768
#define OUT_ 300
#define K4_  3072   // 4*H
#define K3_  2304   // 3*H (GEMM3 after seg-4 fold)

// ---------------- GEMM tiling ----------------
#define BM 128
#define BK 64                  // bf16 k per chunk (128B rows)
#define SWZ(x) ((x) ^ (((x) >> 3) & 0x70))

// ---------------- f32 scratch ----------------
static __device__ __align__(16) float g_s[(size_t)B_ * C_ * Q_];
static __device__ float g_sc[B_ * C_];
static __device__ float g_sq[B_ * Q_];
static __device__ float g_rowmax[B_ * C_];
static __device__ float g_batt[B_ * C_];
static __device__ float g_q2c[B_ * H_];

// ---------------- bf16 hi/lo planes ----------------
static __device__ __align__(16) __nv_bfloat16 p_e2h[(size_t)B_ * C_ * H_];
static __device__ __align__(16) __nv_bfloat16 p_e2l[(size_t)B_ * C_ * H_];
static __device__ __align__(16) __nv_bfloat16 p_b1h[(size_t)B_ * Q_ * H_];   // emb1*w_cq
static __device__ __align__(16) __nv_bfloat16 p_b1l[(size_t)B_ * Q_ * H_];
static __device__ __align__(16) __nv_bfloat16 p_e1th[(size_t)B_ * H_ * Q_];  // emb1^T
static __device__ __align__(16) __nv_bfloat16 p_e1tl[(size_t)B_ * H_ * Q_];
static __device__ __align__(16) __nv_bfloat16 p_ah[(size_t)B_ * C_ * Q_];    // softmax probs
static __device__ __align__(16) __nv_bfloat16 p_al[(size_t)B_ * C_ * Q_];
static __device__ __align__(16) __nv_bfloat16 p_cqh[(size_t)B_ * C_ * H_];   // c2q
static __device__ __align__(16) __nv_bfloat16 p_cql[(size_t)B_ * C_ * H_];
static __device__ __align__(16) __nv_bfloat16 p_ech[(size_t)B_ * C_ * H_];   // emb2*c2q
static __device__ __align__(16) __nv_bfloat16 p_ecl[(size_t)B_ * C_ * H_];
static __device__ __align__(16) __nv_bfloat16 p_w14h[(size_t)B_ * OUT_ * H_]; // w1 + w4*q2c[b]
static __device__ __align__(16) __nv_bfloat16 p_w14l[(size_t)B_ * OUT_ * H_];
static __device__ __align__(16) __nv_bfloat16 p_w23h[(size_t)OUT_ * 2 * H_];  // w2|w3
static __device__ __align__(16) __nv_bfloat16 p_w23l[(size_t)OUT_ * 2 * H_];

// ---------------- asm helpers ----------------
__device__ __forceinline__ uint32_t smem_u32(const void* p) {
    uint32_t a;
    asm("{ .reg .u64 t; cvta.to.shared.u64 t, %1; cvt.u32.u64 %0, t; }" : "=r"(a) : "l"(p));
    return a;
}
__device__ __forceinline__ void cpa16(uint32_t dst, const void* src) {
    asm volatile("cp.async.cg.shared.global [%0], [%1], 16;" :: "r"(dst), "l"(src) : "memory");
}
__device__ __forceinline__ void cpa16z(uint32_t dst, const void* src, int szbytes) {
    asm volatile("cp.async.cg.shared.global [%0], [%1], 16, %2;" :: "r"(dst), "l"(src), "r"(szbytes) : "memory");
}
__device__ __forceinline__ void cpa_commit() {
    asm volatile("cp.async.commit_group;" ::: "memory");
}
template<int N>
__device__ __forceinline__ void cpa_wait() {
    asm volatile("cp.async.wait_group %0;" :: "n"(N) : "memory");
}
__device__ __forceinline__ void ldsm4(uint32_t (&r)[4], uint32_t addr) {
    asm volatile("ldmatrix.sync.aligned.m8n8.x4.shared.b16 {%0,%1,%2,%3}, [%4];"
        : "=r"(r[0]), "=r"(r[1]), "=r"(r[2]), "=r"(r[3]) : "r"(addr));
}
__device__ __forceinline__ void mma_bf16(float (&d)[4], const uint32_t (&a)[4], uint32_t b0, uint32_t b1) {
    asm volatile("mma.sync.aligned.m16n8k16.row.col.f32.bf16.bf16.f32 "
        "{%0,%1,%2,%3}, {%4,%5,%6,%7}, {%8,%9}, {%0,%1,%2,%3};"
        : "+f"(d[0]), "+f"(d[1]), "+f"(d[2]), "+f"(d[3])
        : "r"(a[0]), "r"(a[1]), "r"(a[2]), "r"(a[3]), "r"(b0), "r"(b1));
}

// ---------------- split helpers ----------------
__device__ __forceinline__ void split4(float4 v, uint2& hi, uint2& lo) {
    __nv_bfloat162 h01 = __floats2bfloat162_rn(v.x, v.y);
    __nv_bfloat162 h23 = __floats2bfloat162_rn(v.z, v.w);
    float lx = v.x - __bfloat162float(h01.x);
    float ly = v.y - __bfloat162float(h01.y);
    float lz = v.z - __bfloat162float(h23.x);
    float lw = v.w - __bfloat162float(h23.y);
    __nv_bfloat162 l01 = __floats2bfloat162_rn(lx, ly);
    __nv_bfloat162 l23 = __floats2bfloat162_rn(lz, lw);
    hi.x = *(uint32_t*)&h01; hi.y = *(uint32_t*)&h23;
    lo.x = *(uint32_t*)&l01; lo.y = *(uint32_t*)&l23;
}
__device__ __forceinline__ void write_pair(__nv_bfloat16* ph, __nv_bfloat16* pl,
                                           size_t o, float x, float y) {
    __nv_bfloat162 h = __floats2bfloat162_rn(x, y);
    __nv_bfloat162 l = __floats2bfloat162_rn(x - __bfloat162float(h.x),
                                             y - __bfloat162float(h.y));
    *(__nv_bfloat162*)(ph + o) = h;
    *(__nv_bfloat162*)(pl + o) = l;
}

// ---------------- prep kernels ----------------
__global__ __launch_bounds__(256) void prep_emb2_kernel(const float* __restrict__ emb2) {
    size_t p = ((size_t)blockIdx.x * 256 + threadIdx.x) * 4;
    float4 v = *(const float4*)(emb2 + p);
    uint2 h, l; split4(v, h, l);
    *(uint2*)(p_e2h + p) = h;
    *(uint2*)(p_e2l + p) = l;
}

__global__ __launch_bounds__(256) void prep_b1_kernel(const float* __restrict__ emb1,
                                                      const float* __restrict__ w_cq) {
    size_t p = ((size_t)blockIdx.x * 256 + threadIdx.x) * 4;
    int hcol = (int)(p % H_);
    float4 v = *(const float4*)(emb1 + p);
    float4 w = *(const float4*)(w_cq + hcol);
    v.x *= w.x; v.y *= w.y; v.z *= w.z; v.w *= w.w;
    uint2 h, l; split4(v, h, l);
    *(uint2*)(p_b1h + p) = h;
    *(uint2*)(p_b1l + p) = l;
}

// emb1^T split: e1t[b,h,q] = emb1[b,q,h]
__global__ __launch_bounds__(256) void prep_e1t_kernel(const float* __restrict__ emb1) {
    __shared__ float sm[32][33];
    const int b = blockIdx.z, h0 = blockIdx.y * 32, q0 = blockIdx.x * 32;
    const int tx = threadIdx.x & 31, ty = threadIdx.x >> 5;
    #pragma unroll
    for (int i = 0; i < 4; i++)
        sm[ty + 8 * i][tx] = emb1[(size_t)(b * Q_ + q0 + ty + 8 * i) * H_ + h0 + tx];
    __syncthreads();
    #pragma unroll
    for (int i = 0; i < 4; i++) {
        float v = sm[tx][ty + 8 * i];
        __nv_bfloat16 h = __float2bfloat16(v);
        __nv_bfloat16 l = __float2bfloat16(v - __bfloat162float(h));
        size_t o = (size_t)(b * H_ + h0 + ty + 8 * i) * Q_ + q0 + tx;
        p_e1th[o] = h;
        p_e1tl[o] = l;
    }
}

// w2|w3 planes: p_w23[n, 0:1536] = w_red[n, 768:2304]
__global__ __launch_bounds__(256) void prep_w23_kernel(const float* __restrict__ w_red) {
    size_t p = ((size_t)blockIdx.x * 256 + threadIdx.x) * 4;    // over OUT_*1536
    int col = (int)(p % (2 * H_));
    int n = (int)(p / (2 * H_));
    float4 v = *(const float4*)(w_red + (size_t)n * K4_ + H_ + col);
    uint2 h, l; split4(v, h, l);
    *(uint2*)(p_w23h + p) = h;
    *(uint2*)(p_w23l + p) = l;
}

// w14[b,n,h] = w1[n,h] + w4[n,h] * q2c[b,h]
__global__ __launch_bounds__(256) void prep_w14_kernel(const float* __restrict__ w_red) {
    size_t p = ((size_t)blockIdx.x * 256 + threadIdx.x) * 4;    // over B_*OUT_*H_
    int h = (int)(p % H_);
    int n = (int)((p / H_) % OUT_);
    int b = (int)(p / ((size_t)OUT_ * H_));
    float4 w1 = *(const float4*)(w_red + (size_t)n * K4_ + h);
    float4 w4 = *(const float4*)(w_red + (size_t)n * K4_ + 3 * H_ + h);
    float4 q  = *(const float4*)(g_q2c + b * H_ + h);
    float4 v = make_float4(w1.x + w4.x * q.x, w1.y + w4.y * q.y,
                           w1.z + w4.z * q.z, w1.w + w4.w * q.w);
    uint2 hh, ll; split4(v, hh, ll);
    *(uint2*)(p_w14h + p) = hh;
    *(uint2*)(p_w14l + p) = ll;
}

// ---------------- reduce helpers ----------------
__device__ __forceinline__ float warpMax(float v) {
    #pragma unroll
    for (int o = 16; o > 0; o >>= 1) v = fmaxf(v, __shfl_xor_sync(0xffffffffu, v, o));
    return v;
}
__device__ __forceinline__ float warpSum(float v) {
    #pragma unroll
    for (int o = 16; o > 0; o >>= 1) v += __shfl_xor_sync(0xffffffffu, v, o);
    return v;
}

// ---------------- sc / sq ----------------
__global__ __launch_bounds__(256) void rowdot_kernel(
    const float* __restrict__ X, const float* __restrict__ w,
    const float* __restrict__ bias, int nrows, int which)
{
    int gw = (blockIdx.x * blockDim.x + threadIdx.x) >> 5;
    int lane = threadIdx.x & 31;
    if (gw >= nrows) return;
    const float* x = X + (size_t)gw * H_;
    float s = 0.f;
    #pragma unroll
    for (int i = 0; i < H_ / 32; i++)
        s = fmaf(x[lane + 32 * i], w[lane + 32 * i], s);
    s = warpSum(s);
    if (lane == 0) {
        float r = s + *bias;
        if (which == 0) g_sc[gw] = r; else g_sq[gw] = r;
    }
}

// ---------------- softmax: probs -> bf16 planes, record rowmax ----------------
__global__ __launch_bounds__(256) void softmax_kernel()
{
    const int row = blockIdx.x;
    const float* s = g_s + (size_t)row * Q_;
    const int tid = threadIdx.x;
    const int lane = tid & 31, w = tid >> 5;

    float v0 = s[tid], v1 = s[tid + 256];
    float m = warpMax(fmaxf(v0, v1));
    __shared__ float smx[8];
    if (lane == 0) smx[w] = m;
    __syncthreads();
    if (w == 0) {
        float t = smx[lane & 7];
        t = warpMax(t);
        if (lane == 0) smx[0] = t;
    }
    __syncthreads();
    m = smx[0];
    if (tid == 0) g_rowmax[row] = m;

    float e0 = __expf(v0 - m), e1 = __expf(v1 - m);
    float ss = warpSum(e0 + e1);
    __shared__ float ssm[8];
    if (lane == 0) ssm[w] = ss;
    __syncthreads();
    if (w == 0) {
        float t = (lane < 8) ? ssm[lane] : 0.f;
        t = warpSum(t);
        if (lane == 0) ssm[0] = t;
    }
    __syncthreads();
    float inv = 1.f / ssm[0];
    float p0 = e0 * inv, p1 = e1 * inv;
    size_t o = (size_t)row * Q_;
    __nv_bfloat16 h0 = __float2bfloat16(p0);
    __nv_bfloat16 h1 = __float2bfloat16(p1);
    p_ah[o + tid]       = h0;
    p_ah[o + tid + 256] = h1;
    p_al[o + tid]       = __float2bfloat16(p0 - __bfloat162float(h0));
    p_al[o + tid + 256] = __float2bfloat16(p1 - __bfloat162float(h1));
}

// ---------------- b_att (+ zero q2c accumulator) ----------------
__global__ __launch_bounds__(1024) void batt_kernel()
{
    const int b = blockIdx.x;
    const float* rm = g_rowmax + b * C_;
    const int tid = threadIdx.x;
    const int lane = tid & 31, w = tid >> 5;

    if (tid < H_) g_q2c[b * H_ + tid] = 0.f;

    float v0 = rm[tid], v1 = rm[tid + 1024];
    float m = warpMax(fmaxf(v0, v1));
    __shared__ float smx[32];
    if (lane == 0) smx[w] = m;
    __syncthreads();
    if (w == 0) {
        float t = smx[lane];
        t = warpMax(t);
        if (lane == 0) smx[0] = t;
    }
    __syncthreads();
    m = smx[0];

    float e0 = __expf(v0 - m), e1 = __expf(v1 - m);
    float ss = warpSum(e0 + e1);
    __shared__ float ssm[32];
    if (lane == 0) ssm[w] = ss;
    __syncthreads();
    if (w == 0) {
        float t = ssm[lane];
        t = warpSum(t);
        if (lane == 0) ssm[0] = t;
    }
    __syncthreads();
    float inv = 1.f / ssm[0];
    g_batt[b * C_ + tid]        = e0 * inv;
    g_batt[b * C_ + tid + 1024] = e1 * inv;
}

// ---------------- q2c (split C, atomic accumulate) ----------------
__global__ __launch_bounds__(256) void q2c_kernel(const float* __restrict__ emb2)
{
    const int b = blockIdx.y;
    const int h = blockIdx.x * 256 + threadIdx.x;
    const int c0 = blockIdx.z * 256;
    __shared__ float batt[256];
    batt[threadIdx.x] = g_batt[b * C_ + c0 + threadIdx.x];
    __syncthreads();
    const float* e = emb2 + (size_t)(b * C_ + c0) * H_ + h;
    float acc = 0.f;
    #pragma unroll 8
    for (int c = 0; c < 256; c++)
        acc = fmaf(batt[c], e[(size_t)c * H_], acc);
    atomicAdd(&g_q2c[b * H_ + h], acc);
}

// ---------------- warp-MMA GEMM (split-bf16, mma.sync m16n8k16) ----------------
// D[M x N] = A @ B^T (K-major rows both sides), hi/lo planes, 3 products.
// G=1: A=e2 planes (K=768),   B=b1 planes              -> g_s (+sc+sq+bcq)   BN=128
// G=2: A=prob planes (K=512), B=e1t planes             -> cq/ec planes       BN=128
// G=3: A=[e2|cq|ec] (K=2304), B=[w14(b)|w23] (<300)    -> out (+b_red)       BN=64
template<int G, int BNt, int WN>
__global__ __launch_bounds__(256) void gemm_mma_kernel(const float* __restrict__ aux,
                                                       float* __restrict__ outp)
{
    extern __shared__ __align__(16) char smem[];
    constexpr int OFF_AL_ = 16384;
    constexpr int OFF_BH_ = 32768;
    constexpr int OFF_BL_ = 32768 + BNt * 128;
    constexpr int STAGE_  = 32768 + 2 * BNt * 128;
    constexpr int NBI = BNt / 32;       // B loader iterations
    constexpr int NP  = WN / 16;        // n16 fragment groups per warp
    constexpr int NT  = WN / 8;         // n8 mma tiles per warp

    const uint32_t sbase = smem_u32(smem);
    const int tid = threadIdx.x;
    const int lane = tid & 31, wid = tid >> 5;
    const int b  = blockIdx.z;
    const int m0 = blockIdx.x * BM;
    const int n0 = blockIdx.y * BNt;
    const int m0w = (wid & 3) * 32;
    const int n0w = (wid >> 2) * WN;

    constexpr int KTOT = (G == 1) ? H_ : (G == 2) ? Q_ : K3_;
    constexpr int NC = KTOT / BK;

    // ---- loader lane mapping ----
    int aRow[4], aU[4]; uint32_t aSo[4];
    #pragma unroll
    for (int i = 0; i < 4; i++) {
        int t = tid + 256 * i;
        aRow[i] = t >> 3; aU[i] = t & 7;
        aSo[i] = SWZ((uint32_t)(aRow[i] * 128 + aU[i] * 16));
    }
    int bRow[NBI], bU[NBI]; uint32_t bSo[NBI];
    #pragma unroll
    for (int i = 0; i < NBI; i++) {
        int t = tid + 256 * i;
        bRow[i] = t >> 3; bU[i] = t & 7;
        bSo[i] = SWZ((uint32_t)(bRow[i] * 128 + bU[i] * 16));
    }

    auto load_chunk = [&](int c, int st) {
        const uint32_t S = sbase + (uint32_t)st * STAGE_;
        const int k0 = c * BK;
        // ---- A ----
        const __nv_bfloat16 *pah, *pal;
        size_t abase; int strideA;
        if constexpr (G == 1) {
            pah = p_e2h; pal = p_e2l;
            abase = (size_t)(b * C_ + m0) * H_ + k0; strideA = H_;
        } else if constexpr (G == 2) {
            pah = p_ah; pal = p_al;
            abase = (size_t)(b * C_ + m0) * Q_ + k0; strideA = Q_;
        } else {
            int seg = k0 / H_;
            int koff = k0 - seg * H_;
            pah = (seg == 0) ? p_e2h : (seg == 1) ? p_cqh : p_ech;
            pal = (seg == 0) ? p_e2l : (seg == 1) ? p_cql : p_ecl;
            abase = (size_t)(b * C_ + m0) * H_ + koff; strideA = H_;
        }
        #pragma unroll
        for (int i = 0; i < 4; i++) {
            size_t go = abase + (size_t)aRow[i] * strideA + aU[i] * 8;
            cpa16(S + aSo[i], pah + go);
            cpa16(S + OFF_AL_ + aSo[i], pal + go);
        }
        // ---- B ----
        if constexpr (G == 3) {
            int seg = k0 / H_;
            #pragma unroll
            for (int i = 0; i < NBI; i++) {
                int nrow = n0 + bRow[i];
                int valid = nrow < OUT_ ? 16 : 0;
                int nr = nrow < OUT_ ? nrow : (OUT_ - 1);
                const __nv_bfloat16 *pbh, *pbl;
                size_t go;
                if (seg == 0) {
                    pbh = p_w14h; pbl = p_w14l;
                    go = ((size_t)b * OUT_ + nr) * H_ + k0 + bU[i] * 8;
                } else {
                    pbh = p_w23h; pbl = p_w23l;
                    go = (size_t)nr * (2 * H_) + (k0 - H_) + bU[i] * 8;
                }
                cpa16z(S + OFF_BH_ + bSo[i], pbh + go, valid);
                cpa16z(S + OFF_BL_ + bSo[i], pbl + go, valid);
            }
        } else {
            const __nv_bfloat16 *pbh, *pbl;
            size_t bbase; int strideB;
            if constexpr (G == 1) {
                pbh = p_b1h; pbl = p_b1l;
                bbase = (size_t)(b * Q_ + n0) * H_ + k0; strideB = H_;
            } else {
                pbh = p_e1th; pbl = p_e1tl;
                bbase = (size_t)(b * H_ + n0) * Q_ + k0; strideB = Q_;
            }
            #pragma unroll
            for (int i = 0; i < NBI; i++) {
                size_t go = bbase + (size_t)bRow[i] * strideB + bU[i] * 8;
                cpa16(S + OFF_BH_ + bSo[i], pbh + go);
                cpa16(S + OFF_BL_ + bSo[i], pbl + go);
            }
        }
    };

    // ---- mma lane constants ----
    const int matL = lane >> 3;
    const int rA   = lane & 7;
    const int rowA = (matL & 1) * 8 + rA;
    const int kselA = (matL >> 1) * 16;
    const int xA = rA << 4;
    const int nB   = (matL >> 1) * 8 + rA;
    const int kselB = (matL & 1) * 16;
    const int xB = rA << 4;

    uint32_t aRowByte[2];
    #pragma unroll
    for (int mt = 0; mt < 2; mt++) aRowByte[mt] = (uint32_t)((m0w + mt * 16 + rowA) * 128);
    uint32_t bRowByte[NP];
    #pragma unroll
    for (int np = 0; np < NP; np++) bRowByte[np] = (uint32_t)((n0w + np * 16 + nB) * 128);

    float acc[2][NT][4];
    #pragma unroll
    for (int mt = 0; mt < 2; mt++)
        #pragma unroll
        for (int nt = 0; nt < NT; nt++)
            #pragma unroll
            for (int k = 0; k < 4; k++) acc[mt][nt][k] = 0.f;

    auto compute_chunk = [&](uint32_t S) {
        #pragma unroll
        for (int ks = 0; ks < 4; ks++) {
            uint32_t aH[2][4], aL[2][4], bH[NP][4], bL[NP][4];
            const uint32_t kxA = (uint32_t)((ks * 32 + kselA) ^ xA);
            const uint32_t kxB = (uint32_t)((ks * 32 + kselB) ^ xB);
            #pragma unroll
            for (int mt = 0; mt < 2; mt++) {
                ldsm4(aH[mt], S + aRowByte[mt] + kxA);
                ldsm4(aL[mt], S + OFF_AL_ + aRowByte[mt] + kxA);
            }
            #pragma unroll
            for (int np = 0; np < NP; np++) {
                ldsm4(bH[np], S + OFF_BH_ + bRowByte[np] + kxB);
                ldsm4(bL[np], S + OFF_BL_ + bRowByte[np] + kxB);
            }
            #pragma unroll
            for (int mt = 0; mt < 2; mt++)
                #pragma unroll
                for (int nt = 0; nt < NT; nt++) {
                    uint32_t b0h = bH[nt >> 1][(nt & 1) * 2], b1h = bH[nt >> 1][(nt & 1) * 2 + 1];
                    uint32_t b0l = bL[nt >> 1][(nt & 1) * 2], b1l = bL[nt >> 1][(nt & 1) * 2 + 1];
                    mma_bf16(acc[mt][nt], aH[mt], b0h, b1h);
                    mma_bf16(acc[mt][nt], aH[mt], b0l, b1l);
                    mma_bf16(acc[mt][nt], aL[mt], b0h, b1h);
                }
        }
    };

    // ---- pipeline ----
    load_chunk(0, 0);
    cpa_commit();
    for (int c = 0; c < NC; c++) {
        if (c + 1 < NC) {
            load_chunk(c + 1, (c + 1) & 1);
            cpa_commit();
            cpa_wait<1>();
        } else {
            cpa_wait<0>();
        }
        __syncthreads();
        compute_chunk(sbase + (uint32_t)(c & 1) * STAGE_);
        __syncthreads();
    }

    // ---- epilogue ----
    const int r0l = lane >> 2;
    const int c0l = (lane & 3) * 2;
    #pragma unroll
    for (int mt = 0; mt < 2; mt++) {
        #pragma unroll
        for (int nt = 0; nt < NT; nt++) {
            int rg = b * C_ + m0 + m0w + mt * 16 + r0l;
            int cg = n0 + n0w + nt * 8 + c0l;
            float d0 = acc[mt][nt][0], d1 = acc[mt][nt][1];
            float d2 = acc[mt][nt][2], d3 = acc[mt][nt][3];
            if constexpr (G == 1) {
                float bcq = aux[0];
                float sq0 = g_sq[b * Q_ + cg], sq1 = g_sq[b * Q_ + cg + 1];
                float sc0 = g_sc[rg], sc1 = g_sc[rg + 8];
                *(float2*)(g_s + (size_t)rg * Q_ + cg)       = make_float2(d0 + sc0 + sq0 + bcq, d1 + sc0 + sq1 + bcq);
                *(float2*)(g_s + (size_t)(rg + 8) * Q_ + cg) = make_float2(d2 + sc1 + sq0 + bcq, d3 + sc1 + sq1 + bcq);
            } else if constexpr (G == 2) {
                size_t o0 = (size_t)rg * H_ + cg;
                size_t o1 = (size_t)(rg + 8) * H_ + cg;
                float2 e0 = *(const float2*)(aux + o0);     // emb2
                float2 e1 = *(const float2*)(aux + o1);
                write_pair(p_cqh, p_cql, o0, d0, d1);
                write_pair(p_cqh, p_cql, o1, d2, d3);
                write_pair(p_ech, p_ecl, o0, d0 * e0.x, d1 * e0.y);
                write_pair(p_ech, p_ecl, o1, d2 * e1.x, d3 * e1.y);
            } else {
                if (cg < OUT_) {
                    float b0 = aux[cg], b1 = aux[cg + 1];
                    *(float2*)(outp + (size_t)rg * OUT_ + cg)       = make_float2(d0 + b0, d1 + b1);
                    *(float2*)(outp + (size_t)(rg + 8) * OUT_ + cg) = make_float2(d2 + b0, d3 + b1);
                }
            }
        }
    }
}

#define SMEM_G12 (2 * (32768 + 2 * 128 * 128))   // 131072
#define SMEM_G3  (2 * (32768 + 2 * 64 * 128))    // 98304

// ---------------- launch ----------------
extern "C" void kernel_launch(void* const* d_in, const int* in_sizes, int n_in,
                              void* d_out, int out_size)
{
    const float* emb1  = (const float*)d_in[0];
    const float* emb2  = (const float*)d_in[1];
    const float* w_c   = (const float*)d_in[2];
    const float* b_c   = (const float*)d_in[3];
    const float* w_q   = (const float*)d_in[4];
    const float* b_q   = (const float*)d_in[5];
    const float* w_cq  = (const float*)d_in[6];
    const float* b_cq  = (const float*)d_in[7];
    const float* w_red = (const float*)d_in[8];
    const float* b_red = (const float*)d_in[9];
    float* out = (float*)d_out;

    cudaFuncSetAttribute((const void*)gemm_mma_kernel<1, 128, 64>, cudaFuncAttributeMaxDynamicSharedMemorySize, SMEM_G12);
    cudaFuncSetAttribute((const void*)gemm_mma_kernel<2, 128, 64>, cudaFuncAttributeMaxDynamicSharedMemorySize, SMEM_G12);
    cudaFuncSetAttribute((const void*)gemm_mma_kernel<3, 64, 32>,  cudaFuncAttributeMaxDynamicSharedMemorySize, SMEM_G3);

    // launches 0-4 (gemm1 must be launch index 5 so ncu -s 5 profiles it)
    prep_emb2_kernel<<<(int)((size_t)B_ * C_ * H_ / 4 / 256), 256>>>(emb2);
    prep_b1_kernel<<<(int)((size_t)B_ * Q_ * H_ / 4 / 256), 256>>>(emb1, w_cq);
    rowdot_kernel<<<(B_ * C_ * 32) / 256, 256>>>(emb2, w_c, b_c, B_ * C_, 0);
    rowdot_kernel<<<(B_ * Q_ * 32) / 256, 256>>>(emb1, w_q, b_q, B_ * Q_, 1);
    prep_e1t_kernel<<<dim3(Q_ / 32, H_ / 32, B_), 256>>>(emb1);

    // GEMM1 (launch 5): s = emb2 @ (emb1*w_cq)^T + sc + sq + bcq
    gemm_mma_kernel<1, 128, 64><<<dim3(C_ / BM, Q_ / 128, B_), 256, SMEM_G12>>>(b_cq, nullptr);

    // softmax (probs -> planes), batt(+q2c zero), q2c, fused weights
    softmax_kernel<<<B_ * C_, 256>>>();
    batt_kernel<<<B_, 1024>>>();
    q2c_kernel<<<dim3(H_ / 256, B_, C_ / 256), 256>>>(emb2);
    prep_w14_kernel<<<(int)((size_t)B_ * OUT_ * H_ / 4 / 256), 256>>>(w_red);
    prep_w23_kernel<<<(int)((size_t)OUT_ * 2 * H_ / 4 / 256), 256>>>(w_red);

    // GEMM2: c2q = a @ emb1  (epilogue writes cq / e2*cq planes directly)
    gemm_mma_kernel<2, 128, 64><<<dim3(C_ / BM, H_ / 128, B_), 256, SMEM_G12>>>(emb2, nullptr);

    // GEMM3: out = [e2 | cq | e2*cq] @ [w14(b) | w2 | w3]^T + b_red
    gemm_mma_kernel<3, 64, 32><<<dim3(C_ / BM, (OUT_ + 63) / 64, B_), 256, SMEM_G3>>>(b_red, out);
}

// round 7
// speedup vs baseline: 1.1335x; 1.1335x over previous
#include <cuda_runtime.h>
#include <cuda_bf16.h>
#include <cstdint>

// ---------------- problem constants ----------------
#define B_   8
#define Q_   512
#define C_   2048
#define H_   768
#define OUT_ 300
#define K4_  3072   // 4*H
#define K3_  2304   // 3*H (GEMM3 after seg-4 fold)

// ---------------- GEMM tiling ----------------
#define BM 128
#define BN 64
#define BK 64                  // bf16 k per chunk (128B rows)
#define OFF_AL 16384
#define OFF_BH 32768
#define OFF_BL 40960
#define STAGE_BYTES 49152
#define SMEM_TOTAL (2 * STAGE_BYTES)   // 96 KB -> 2 CTAs/SM

#define SWZ(x) ((x) ^ (((x) >> 3) & 0x70))

// ---------------- f32 scratch ----------------
static __device__ __align__(16) float g_s[(size_t)B_ * C_ * Q_];
static __device__ float g_sc[B_ * C_];
static __device__ float g_sq[B_ * Q_];
static __device__ float g_rowmax[B_ * C_];
static __device__ float g_batt[B_ * C_];
static __device__ float g_q2c[B_ * H_];

// ---------------- bf16 hi/lo planes ----------------
static __device__ __align__(16) __nv_bfloat16 p_e2h[(size_t)B_ * C_ * H_];
static __device__ __align__(16) __nv_bfloat16 p_e2l[(size_t)B_ * C_ * H_];
static __device__ __align__(16) __nv_bfloat16 p_b1h[(size_t)B_ * Q_ * H_];   // emb1*w_cq
static __device__ __align__(16) __nv_bfloat16 p_b1l[(size_t)B_ * Q_ * H_];
static __device__ __align__(16) __nv_bfloat16 p_e1th[(size_t)B_ * H_ * Q_];  // emb1^T
static __device__ __align__(16) __nv_bfloat16 p_e1tl[(size_t)B_ * H_ * Q_];
static __device__ __align__(16) __nv_bfloat16 p_ah[(size_t)B_ * C_ * Q_];    // softmax probs
static __device__ __align__(16) __nv_bfloat16 p_al[(size_t)B_ * C_ * Q_];
static __device__ __align__(16) __nv_bfloat16 p_cqh[(size_t)B_ * C_ * H_];   // c2q
static __device__ __align__(16) __nv_bfloat16 p_cql[(size_t)B_ * C_ * H_];
static __device__ __align__(16) __nv_bfloat16 p_ech[(size_t)B_ * C_ * H_];   // emb2*c2q
static __device__ __align__(16) __nv_bfloat16 p_ecl[(size_t)B_ * C_ * H_];
static __device__ __align__(16) __nv_bfloat16 p_w14h[(size_t)B_ * OUT_ * H_]; // w1 + w4*q2c[b]
static __device__ __align__(16) __nv_bfloat16 p_w14l[(size_t)B_ * OUT_ * H_];
static __device__ __align__(16) __nv_bfloat16 p_w23h[(size_t)OUT_ * 2 * H_];  // w2|w3
static __device__ __align__(16) __nv_bfloat16 p_w23l[(size_t)OUT_ * 2 * H_];

// ---------------- asm helpers ----------------
__device__ __forceinline__ uint32_t smem_u32(const void* p) {
    uint32_t a;
    asm("{ .reg .u64 t; cvta.to.shared.u64 t, %1; cvt.u32.u64 %0, t; }" : "=r"(a) : "l"(p));
    return a;
}
__device__ __forceinline__ void cpa16(uint32_t dst, const void* src) {
    asm volatile("cp.async.cg.shared.global [%0], [%1], 16;" :: "r"(dst), "l"(src) : "memory");
}
__device__ __forceinline__ void cpa16z(uint32_t dst, const void* src, int szbytes) {
    asm volatile("cp.async.cg.shared.global [%0], [%1], 16, %2;" :: "r"(dst), "l"(src), "r"(szbytes) : "memory");
}
__device__ __forceinline__ void cpa_commit() {
    asm volatile("cp.async.commit_group;" ::: "memory");
}
template<int N>
__device__ __forceinline__ void cpa_wait() {
    asm volatile("cp.async.wait_group %0;" :: "n"(N) : "memory");
}
__device__ __forceinline__ void ldsm4(uint32_t (&r)[4], uint32_t addr) {
    asm volatile("ldmatrix.sync.aligned.m8n8.x4.shared.b16 {%0,%1,%2,%3}, [%4];"
        : "=r"(r[0]), "=r"(r[1]), "=r"(r[2]), "=r"(r[3]) : "r"(addr));
}
__device__ __forceinline__ void mma_bf16(float (&d)[4], const uint32_t (&a)[4], uint32_t b0, uint32_t b1) {
    asm volatile("mma.sync.aligned.m16n8k16.row.col.f32.bf16.bf16.f32 "
        "{%0,%1,%2,%3}, {%4,%5,%6,%7}, {%8,%9}, {%0,%1,%2,%3};"
        : "+f"(d[0]), "+f"(d[1]), "+f"(d[2]), "+f"(d[3])
        : "r"(a[0]), "r"(a[1]), "r"(a[2]), "r"(a[3]), "r"(b0), "r"(b1));
}

// ---------------- split helpers ----------------
__device__ __forceinline__ void split4(float4 v, uint2& hi, uint2& lo) {
    __nv_bfloat162 h01 = __floats2bfloat162_rn(v.x, v.y);
    __nv_bfloat162 h23 = __floats2bfloat162_rn(v.z, v.w);
    float lx = v.x - __bfloat162float(h01.x);
    float ly = v.y - __bfloat162float(h01.y);
    float lz = v.z - __bfloat162float(h23.x);
    float lw = v.w - __bfloat162float(h23.y);
    __nv_bfloat162 l01 = __floats2bfloat162_rn(lx, ly);
    __nv_bfloat162 l23 = __floats2bfloat162_rn(lz, lw);
    hi.x = *(uint32_t*)&h01; hi.y = *(uint32_t*)&h23;
    lo.x = *(uint32_t*)&l01; lo.y = *(uint32_t*)&l23;
}
__device__ __forceinline__ void write_pair(__nv_bfloat16* ph, __nv_bfloat16* pl,
                                           size_t o, float x, float y) {
    __nv_bfloat162 h = __floats2bfloat162_rn(x, y);
    __nv_bfloat162 l = __floats2bfloat162_rn(x - __bfloat162float(h.x),
                                             y - __bfloat162float(h.y));
    *(__nv_bfloat162*)(ph + o) = h;
    *(__nv_bfloat162*)(pl + o) = l;
}

// ---------------- prep kernels ----------------
__global__ __launch_bounds__(256) void prep_emb2_kernel(const float* __restrict__ emb2) {
    size_t p = ((size_t)blockIdx.x * 256 + threadIdx.x) * 4;
    float4 v = *(const float4*)(emb2 + p);
    uint2 h, l; split4(v, h, l);
    *(uint2*)(p_e2h + p) = h;
    *(uint2*)(p_e2l + p) = l;
}

__global__ __launch_bounds__(256) void prep_b1_kernel(const float* __restrict__ emb1,
                                                      const float* __restrict__ w_cq) {
    size_t p = ((size_t)blockIdx.x * 256 + threadIdx.x) * 4;
    int hcol = (int)(p % H_);
    float4 v = *(const float4*)(emb1 + p);
    float4 w = *(const float4*)(w_cq + hcol);
    v.x *= w.x; v.y *= w.y; v.z *= w.z; v.w *= w.w;
    uint2 h, l; split4(v, h, l);
    *(uint2*)(p_b1h + p) = h;
    *(uint2*)(p_b1l + p) = l;
}

// emb1^T split: e1t[b,h,q] = emb1[b,q,h]
__global__ __launch_bounds__(256) void prep_e1t_kernel(const float* __restrict__ emb1) {
    __shared__ float sm[32][33];
    const int b = blockIdx.z, h0 = blockIdx.y * 32, q0 = blockIdx.x * 32;
    const int tx = threadIdx.x & 31, ty = threadIdx.x >> 5;
    #pragma unroll
    for (int i = 0; i < 4; i++)
        sm[ty + 8 * i][tx] = emb1[(size_t)(b * Q_ + q0 + ty + 8 * i) * H_ + h0 + tx];
    __syncthreads();
    #pragma unroll
    for (int i = 0; i < 4; i++) {
        float v = sm[tx][ty + 8 * i];
        __nv_bfloat16 h = __float2bfloat16(v);
        __nv_bfloat16 l = __float2bfloat16(v - __bfloat162float(h));
        size_t o = (size_t)(b * H_ + h0 + ty + 8 * i) * Q_ + q0 + tx;
        p_e1th[o] = h;
        p_e1tl[o] = l;
    }
}

// w2|w3 planes: p_w23[n, 0:1536] = w_red[n, 768:2304]
__global__ __launch_bounds__(256) void prep_w23_kernel(const float* __restrict__ w_red) {
    size_t p = ((size_t)blockIdx.x * 256 + threadIdx.x) * 4;    // over OUT_*1536
    int col = (int)(p % (2 * H_));
    int n = (int)(p / (2 * H_));
    float4 v = *(const float4*)(w_red + (size_t)n * K4_ + H_ + col);
    uint2 h, l; split4(v, h, l);
    *(uint2*)(p_w23h + p) = h;
    *(uint2*)(p_w23l + p) = l;
}

// w14[b,n,h] = w1[n,h] + w4[n,h] * q2c[b,h]
__global__ __launch_bounds__(256) void prep_w14_kernel(const float* __restrict__ w_red) {
    size_t p = ((size_t)blockIdx.x * 256 + threadIdx.x) * 4;    // over B_*OUT_*H_
    int h = (int)(p % H_);
    int n = (int)((p / H_) % OUT_);
    int b = (int)(p / ((size_t)OUT_ * H_));
    float4 w1 = *(const float4*)(w_red + (size_t)n * K4_ + h);
    float4 w4 = *(const float4*)(w_red + (size_t)n * K4_ + 3 * H_ + h);
    float4 q  = *(const float4*)(g_q2c + b * H_ + h);
    float4 v = make_float4(w1.x + w4.x * q.x, w1.y + w4.y * q.y,
                           w1.z + w4.z * q.z, w1.w + w4.w * q.w);
    uint2 hh, ll; split4(v, hh, ll);
    *(uint2*)(p_w14h + p) = hh;
    *(uint2*)(p_w14l + p) = ll;
}

// ---------------- reduce helpers ----------------
__device__ __forceinline__ float warpMax(float v) {
    #pragma unroll
    for (int o = 16; o > 0; o >>= 1) v = fmaxf(v, __shfl_xor_sync(0xffffffffu, v, o));
    return v;
}
__device__ __forceinline__ float warpSum(float v) {
    #pragma unroll
    for (int o = 16; o > 0; o >>= 1) v += __shfl_xor_sync(0xffffffffu, v, o);
    return v;
}

// ---------------- sc and sq fused: one warp per row ----------------
__global__ __launch_bounds__(256) void rowdot2_kernel(
    const float* __restrict__ emb2, const float* __restrict__ emb1,
    const float* __restrict__ w_c, const float* __restrict__ w_q,
    const float* __restrict__ b_c, const float* __restrict__ b_q)
{
    int gw = (blockIdx.x * blockDim.x + threadIdx.x) >> 5;
    int lane = threadIdx.x & 31;
    const float* x; const float* w; float* o; float bias;
    if (gw < B_ * C_) {
        x = emb2 + (size_t)gw * H_; w = w_c; o = g_sc + gw; bias = *b_c;
    } else {
        int g = gw - B_ * C_;
        if (g >= B_ * Q_) return;
        x = emb1 + (size_t)g * H_; w = w_q; o = g_sq + g; bias = *b_q;
    }
    float s = 0.f;
    #pragma unroll
    for (int i = 0; i < H_ / 128; i++) {
        float4 xv = *(const float4*)(x + (lane + 32 * i) * 4);
        float4 wv = *(const float4*)(w + (lane + 32 * i) * 4);
        s = fmaf(xv.x, wv.x, s); s = fmaf(xv.y, wv.y, s);
        s = fmaf(xv.z, wv.z, s); s = fmaf(xv.w, wv.w, s);
    }
    s = warpSum(s);
    if (lane == 0) *o = s + bias;
}

// ---------------- softmax: one warp per row, shfl-only ----------------
__global__ __launch_bounds__(256) void softmax_kernel()
{
    const int row = blockIdx.x * 8 + (threadIdx.x >> 5);
    const int lane = threadIdx.x & 31;
    const float* s = g_s + (size_t)row * Q_;

    float4 v[4];
    float m = -3.4e38f;
    #pragma unroll
    for (int i = 0; i < 4; i++) {
        v[i] = *(const float4*)(s + (lane + 32 * i) * 4);
        m = fmaxf(m, fmaxf(fmaxf(v[i].x, v[i].y), fmaxf(v[i].z, v[i].w)));
    }
    m = warpMax(m);
    if (lane == 0) g_rowmax[row] = m;

    float ss = 0.f;
    #pragma unroll
    for (int i = 0; i < 4; i++) {
        v[i].x = __expf(v[i].x - m); v[i].y = __expf(v[i].y - m);
        v[i].z = __expf(v[i].z - m); v[i].w = __expf(v[i].w - m);
        ss += (v[i].x + v[i].y) + (v[i].z + v[i].w);
    }
    ss = warpSum(ss);
    float inv = 1.f / ss;

    #pragma unroll
    for (int i = 0; i < 4; i++) {
        float4 p = make_float4(v[i].x * inv, v[i].y * inv, v[i].z * inv, v[i].w * inv);
        uint2 h, l; split4(p, h, l);
        size_t o = (size_t)row * Q_ + (lane + 32 * i) * 4;
        *(uint2*)(p_ah + o) = h;
        *(uint2*)(p_al + o) = l;
    }
}

// ---------------- b_att (+ zero q2c accumulator) ----------------
__global__ __launch_bounds__(1024) void batt_kernel()
{
    const int b = blockIdx.x;
    const float* rm = g_rowmax + b * C_;
    const int tid = threadIdx.x;
    const int lane = tid & 31, w = tid >> 5;

    if (tid < H_) g_q2c[b * H_ + tid] = 0.f;

    float v0 = rm[tid], v1 = rm[tid + 1024];
    float m = warpMax(fmaxf(v0, v1));
    __shared__ float smx[32];
    if (lane == 0) smx[w] = m;
    __syncthreads();
    if (w == 0) {
        float t = smx[lane];
        t = warpMax(t);
        if (lane == 0) smx[0] = t;
    }
    __syncthreads();
    m = smx[0];

    float e0 = __expf(v0 - m), e1 = __expf(v1 - m);
    float ss = warpSum(e0 + e1);
    __shared__ float ssm[32];
    if (lane == 0) ssm[w] = ss;
    __syncthreads();
    if (w == 0) {
        float t = ssm[lane];
        t = warpSum(t);
        if (lane == 0) ssm[0] = t;
    }
    __syncthreads();
    float inv = 1.f / ssm[0];
    g_batt[b * C_ + tid]        = e0 * inv;
    g_batt[b * C_ + tid + 1024] = e1 * inv;
}

// ---------------- q2c (split C, atomic accumulate) ----------------
__global__ __launch_bounds__(256) void q2c_kernel(const float* __restrict__ emb2)
{
    const int b = blockIdx.y;
    const int h = blockIdx.x * 256 + threadIdx.x;
    const int c0 = blockIdx.z * 256;
    __shared__ float batt[256];
    batt[threadIdx.x] = g_batt[b * C_ + c0 + threadIdx.x];
    __syncthreads();
    const float* e = emb2 + (size_t)(b * C_ + c0) * H_ + h;
    float acc = 0.f;
    #pragma unroll 8
    for (int c = 0; c < 256; c++)
        acc = fmaf(batt[c], e[(size_t)c * H_], acc);
    atomicAdd(&g_q2c[b * H_ + h], acc);
}

// ---------------- warp-MMA GEMM (split-bf16, mma.sync m16n8k16) ----------------
// D[M x N] = A @ B^T (K-major rows both sides), hi/lo planes, 3 products.
// G=1: A=e2 planes (K=768),   B=b1 planes              -> g_s (+sc+sq+bcq)
// G=2: A=prob planes (K=512), B=e1t planes             -> cq/ec planes (fused)
// G=3: A=[e2|cq|ec] (K=2304), B=[w14(b)|w23] (<300)    -> out (+b_red)
template<int G>
__global__ __launch_bounds__(256) void gemm_mma_kernel(const float* __restrict__ aux,
                                                       float* __restrict__ outp)
{
    extern __shared__ __align__(16) char smem[];
    const uint32_t sbase = smem_u32(smem);
    const int tid = threadIdx.x;
    const int lane = tid & 31, wid = tid >> 5;
    const int b  = blockIdx.z;
    const int m0 = blockIdx.x * BM;
    const int n0 = blockIdx.y * BN;
    const int m0w = (wid & 3) * 32;
    const int n0w = (wid >> 2) * 32;

    constexpr int KTOT = (G == 1) ? H_ : (G == 2) ? Q_ : K3_;
    constexpr int NC = KTOT / BK;

    // ---- loader lane mapping ----
    int aRow[4], aU[4]; uint32_t aSo[4];
    #pragma unroll
    for (int i = 0; i < 4; i++) {
        int t = tid + 256 * i;
        aRow[i] = t >> 3; aU[i] = t & 7;
        aSo[i] = SWZ((uint32_t)(aRow[i] * 128 + aU[i] * 16));
    }
    int bRow[2], bU[2]; uint32_t bSo[2];
    #pragma unroll
    for (int i = 0; i < 2; i++) {
        int t = tid + 256 * i;
        bRow[i] = t >> 3; bU[i] = t & 7;
        bSo[i] = SWZ((uint32_t)(bRow[i] * 128 + bU[i] * 16));
    }

    auto load_chunk = [&](int c, int st) {
        const uint32_t S = sbase + (uint32_t)st * STAGE_BYTES;
        const int k0 = c * BK;
        // ---- A ----
        const __nv_bfloat16 *pah, *pal;
        size_t abase; int strideA;
        if constexpr (G == 1) {
            pah = p_e2h; pal = p_e2l;
            abase = (size_t)(b * C_ + m0) * H_ + k0; strideA = H_;
        } else if constexpr (G == 2) {
            pah = p_ah; pal = p_al;
            abase = (size_t)(b * C_ + m0) * Q_ + k0; strideA = Q_;
        } else {
            int seg = k0 / H_;
            int koff = k0 - seg * H_;
            pah = (seg == 0) ? p_e2h : (seg == 1) ? p_cqh : p_ech;
            pal = (seg == 0) ? p_e2l : (seg == 1) ? p_cql : p_ecl;
            abase = (size_t)(b * C_ + m0) * H_ + koff; strideA = H_;
        }
        #pragma unroll
        for (int i = 0; i < 4; i++) {
            size_t go = abase + (size_t)aRow[i] * strideA + aU[i] * 8;
            cpa16(S + aSo[i], pah + go);
            cpa16(S + OFF_AL + aSo[i], pal + go);
        }
        // ---- B ----
        if constexpr (G == 3) {
            int seg = k0 / H_;
            #pragma unroll
            for (int i = 0; i < 2; i++) {
                int nrow = n0 + bRow[i];
                int valid = nrow < OUT_ ? 16 : 0;
                int nr = nrow < OUT_ ? nrow : (OUT_ - 1);
                const __nv_bfloat16 *pbh, *pbl;
                size_t go;
                if (seg == 0) {
                    pbh = p_w14h; pbl = p_w14l;
                    go = ((size_t)b * OUT_ + nr) * H_ + k0 + bU[i] * 8;
                } else {
                    pbh = p_w23h; pbl = p_w23l;
                    go = (size_t)nr * (2 * H_) + (k0 - H_) + bU[i] * 8;
                }
                cpa16z(S + OFF_BH + bSo[i], pbh + go, valid);
                cpa16z(S + OFF_BL + bSo[i], pbl + go, valid);
            }
        } else {
            const __nv_bfloat16 *pbh, *pbl;
            size_t bbase; int strideB;
            if constexpr (G == 1) {
                pbh = p_b1h; pbl = p_b1l;
                bbase = (size_t)(b * Q_ + n0) * H_ + k0; strideB = H_;
            } else {
                pbh = p_e1th; pbl = p_e1tl;
                bbase = (size_t)(b * H_ + n0) * Q_ + k0; strideB = Q_;
            }
            #pragma unroll
            for (int i = 0; i < 2; i++) {
                size_t go = bbase + (size_t)bRow[i] * strideB + bU[i] * 8;
                cpa16(S + OFF_BH + bSo[i], pbh + go);
                cpa16(S + OFF_BL + bSo[i], pbl + go);
            }
        }
    };

    // ---- mma lane constants ----
    const int matL = lane >> 3;
    const int rA   = lane & 7;
    const int rowA = (matL & 1) * 8 + rA;
    const int kselA = (matL >> 1) * 16;
    const int xA = rA << 4;
    const int nB   = (matL >> 1) * 8 + rA;
    const int kselB = (matL & 1) * 16;
    const int xB = rA << 4;

    uint32_t aRowByte[2], bRowByte[2];
    #pragma unroll
    for (int mt = 0; mt < 2; mt++) aRowByte[mt] = (uint32_t)((m0w + mt * 16 + rowA) * 128);
    #pragma unroll
    for (int np = 0; np < 2; np++) bRowByte[np] = (uint32_t)((n0w + np * 16 + nB) * 128);

    float acc[2][4][4];
    #pragma unroll
    for (int mt = 0; mt < 2; mt++)
        #pragma unroll
        for (int nt = 0; nt < 4; nt++)
            #pragma unroll
            for (int k = 0; k < 4; k++) acc[mt][nt][k] = 0.f;

    auto compute_chunk = [&](uint32_t S) {
        #pragma unroll
        for (int ks = 0; ks < 4; ks++) {
            uint32_t aH[2][4], aL[2][4], bH[2][4], bL[2][4];
            const uint32_t kxA = (uint32_t)((ks * 32 + kselA) ^ xA);
            const uint32_t kxB = (uint32_t)((ks * 32 + kselB) ^ xB);
            #pragma unroll
            for (int mt = 0; mt < 2; mt++) {
                ldsm4(aH[mt], S + aRowByte[mt] + kxA);
                ldsm4(aL[mt], S + OFF_AL + aRowByte[mt] + kxA);
            }
            #pragma unroll
            for (int np = 0; np < 2; np++) {
                ldsm4(bH[np], S + OFF_BH + bRowByte[np] + kxB);
                ldsm4(bL[np], S + OFF_BL + bRowByte[np] + kxB);
            }
            #pragma unroll
            for (int mt = 0; mt < 2; mt++)
                #pragma unroll
                for (int nt = 0; nt < 4; nt++) {
                    uint32_t b0h = bH[nt >> 1][(nt & 1) * 2], b1h = bH[nt >> 1][(nt & 1) * 2 + 1];
                    uint32_t b0l = bL[nt >> 1][(nt & 1) * 2], b1l = bL[nt >> 1][(nt & 1) * 2 + 1];
                    mma_bf16(acc[mt][nt], aH[mt], b0h, b1h);
                    mma_bf16(acc[mt][nt], aH[mt], b0l, b1l);
                    mma_bf16(acc[mt][nt], aL[mt], b0h, b1h);
                }
        }
    };

    // ---- single-sync pipeline ----
    load_chunk(0, 0);
    cpa_commit();
    for (int c = 0; c < NC; c++) {
        cpa_wait<0>();               // only load(c) outstanding here
        __syncthreads();             // publishes stage c AND proves compute(c-1) done
        if (c + 1 < NC) {
            load_chunk(c + 1, (c + 1) & 1);   // safe: stage c^1 free
            cpa_commit();
        }
        compute_chunk(sbase + (uint32_t)(c & 1) * STAGE_BYTES);
    }

    // ---- epilogue ----
    const int r0l = lane >> 2;
    const int c0l = (lane & 3) * 2;
    #pragma unroll
    for (int mt = 0; mt < 2; mt++) {
        #pragma unroll
        for (int nt = 0; nt < 4; nt++) {
            int rg = b * C_ + m0 + m0w + mt * 16 + r0l;
            int cg = n0 + n0w + nt * 8 + c0l;
            float d0 = acc[mt][nt][0], d1 = acc[mt][nt][1];
            float d2 = acc[mt][nt][2], d3 = acc[mt][nt][3];
            if constexpr (G == 1) {
                float bcq = aux[0];
                float sq0 = g_sq[b * Q_ + cg], sq1 = g_sq[b * Q_ + cg + 1];
                float sc0 = g_sc[rg], sc1 = g_sc[rg + 8];
                *(float2*)(g_s + (size_t)rg * Q_ + cg)       = make_float2(d0 + sc0 + sq0 + bcq, d1 + sc0 + sq1 + bcq);
                *(float2*)(g_s + (size_t)(rg + 8) * Q_ + cg) = make_float2(d2 + sc1 + sq0 + bcq, d3 + sc1 + sq1 + bcq);
            } else if constexpr (G == 2) {
                size_t o0 = (size_t)rg * H_ + cg;
                size_t o1 = (size_t)(rg + 8) * H_ + cg;
                float2 e0 = *(const float2*)(aux + o0);     // emb2
                float2 e1 = *(const float2*)(aux + o1);
                write_pair(p_cqh, p_cql, o0, d0, d1);
                write_pair(p_cqh, p_cql, o1, d2, d3);
                write_pair(p_ech, p_ecl, o0, d0 * e0.x, d1 * e0.y);
                write_pair(p_ech, p_ecl, o1, d2 * e1.x, d3 * e1.y);
            } else {
                if (cg < OUT_) {
                    float b0 = aux[cg], b1 = aux[cg + 1];
                    *(float2*)(outp + (size_t)rg * OUT_ + cg)       = make_float2(d0 + b0, d1 + b1);
                    *(float2*)(outp + (size_t)(rg + 8) * OUT_ + cg) = make_float2(d2 + b0, d3 + b1);
                }
            }
        }
    }
}

// ---------------- launch ----------------
extern "C" void kernel_launch(void* const* d_in, const int* in_sizes, int n_in,
                              void* d_out, int out_size)
{
    const float* emb1  = (const float*)d_in[0];
    const float* emb2  = (const float*)d_in[1];
    const float* w_c   = (const float*)d_in[2];
    const float* b_c   = (const float*)d_in[3];
    const float* w_q   = (const float*)d_in[4];
    const float* b_q   = (const float*)d_in[5];
    const float* w_cq  = (const float*)d_in[6];
    const float* b_cq  = (const float*)d_in[7];
    const float* w_red = (const float*)d_in[8];
    const float* b_red = (const float*)d_in[9];
    float* out = (float*)d_out;

    cudaFuncSetAttribute(gemm_mma_kernel<1>, cudaFuncAttributeMaxDynamicSharedMemorySize, SMEM_TOTAL);
    cudaFuncSetAttribute(gemm_mma_kernel<2>, cudaFuncAttributeMaxDynamicSharedMemorySize, SMEM_TOTAL);
    cudaFuncSetAttribute(gemm_mma_kernel<3>, cudaFuncAttributeMaxDynamicSharedMemorySize, SMEM_TOTAL);

    // preps + small dots
    prep_emb2_kernel<<<(int)((size_t)B_ * C_ * H_ / 4 / 256), 256>>>(emb2);
    prep_b1_kernel<<<(int)((size_t)B_ * Q_ * H_ / 4 / 256), 256>>>(emb1, w_cq);
    rowdot2_kernel<<<((B_ * C_ + B_ * Q_) * 32 + 255) / 256, 256>>>(emb2, emb1, w_c, w_q, b_c, b_q);
    prep_e1t_kernel<<<dim3(Q_ / 32, H_ / 32, B_), 256>>>(emb1);
    prep_w23_kernel<<<(int)((size_t)OUT_ * 2 * H_ / 4 / 256), 256>>>(w_red);

    // GEMM1: s = emb2 @ (emb1*w_cq)^T + sc + sq + bcq
    gemm_mma_kernel<1><<<dim3(C_ / BM, Q_ / BN, B_), 256, SMEM_TOTAL>>>(b_cq, nullptr);

    // softmax (probs -> planes), batt(+q2c zero), q2c, fused weights
    softmax_kernel<<<B_ * C_ / 8, 256>>>();
    batt_kernel<<<B_, 1024>>>();
    q2c_kernel<<<dim3(H_ / 256, B_, C_ / 256), 256>>>(emb2);
    prep_w14_kernel<<<(int)((size_t)B_ * OUT_ * H_ / 4 / 256), 256>>>(w_red);

    // GEMM2: c2q = a @ emb1  (epilogue writes cq / e2*cq planes directly)
    gemm_mma_kernel<2><<<dim3(C_ / BM, H_ / BN, B_), 256, SMEM_TOTAL>>>(emb2, nullptr);

    // GEMM3: out = [e2 | cq | e2*cq] @ [w14(b) | w2 | w3]^T + b_red
    gemm_mma_kernel<3><<<dim3(C_ / BM, (OUT_ + BN - 1) / BN, B_), 256, SMEM_TOTAL>>>(b_red, out);
}